// round 11
// baseline (speedup 1.0000x reference)
#include <cuda_runtime.h>
#include <cuda_bf16.h>
#include <math.h>
#include <stdint.h>

#define NNODES 100000
#define NEDGES 1600000
#define NLAB   200000
#define TOTE   (NEDGES + NNODES)

// ---------------- scratch (device globals; no allocation allowed) ----------------
__device__ int   g_deg[NNODES];
__device__ float g_dis[NNODES];
__device__ int   g_row[NNODES + 1];
__device__ int   g_cnt[NNODES];
__device__ int   g_bsum[128];
__device__ int   g_arrive;               // cooperative-scan arrival counter
__device__ int2  g_csr[TOTE];            // packed (src, weight-bits)
__device__ float g_bufA[(size_t)NNODES * 128];
__device__ float g_bufB[(size_t)NNODES * 128];

// ---------------- warp-mma helpers (sm_80+ baseline ISA; no 'a' features) ----------------
__device__ __forceinline__ uint32_t smem_u32(const void* p) {
    uint32_t a;
    asm("{ .reg .u64 t; cvta.to.shared.u64 t, %1; cvt.u32.u64 %0, t; }" : "=r"(a) : "l"(p));
    return a;
}
__device__ __forceinline__ void ldsm_x4(uint32_t* r, uint32_t addr) {
    asm volatile("ldmatrix.sync.aligned.m8n8.x4.shared.b16 {%0,%1,%2,%3}, [%4];"
        : "=r"(r[0]), "=r"(r[1]), "=r"(r[2]), "=r"(r[3]) : "r"(addr));
}
__device__ __forceinline__ void mma_bf16(float* c, const uint32_t* a, const uint32_t* b) {
    asm volatile("mma.sync.aligned.m16n8k16.row.col.f32.bf16.bf16.f32 "
        "{%0,%1,%2,%3}, {%4,%5,%6,%7}, {%8,%9}, {%0,%1,%2,%3};"
        : "+f"(c[0]), "+f"(c[1]), "+f"(c[2]), "+f"(c[3])
        : "r"(a[0]), "r"(a[1]), "r"(a[2]), "r"(a[3]), "r"(b[0]), "r"(b[1]));
}

// ---------------- CSR build ----------------
__global__ void k_init(void) {
    int i = blockIdx.x * blockDim.x + threadIdx.x;
    if (i < NNODES) { g_deg[i] = 1; g_cnt[i] = 0; }
    if (i == 0) g_arrive = 0;
}
__global__ void k_count(const int* __restrict__ ei) {
    int e = blockIdx.x * blockDim.x + threadIdx.x;
    if (e < NEDGES) atomicAdd(&g_deg[ei[NEDGES + e]], 1);
}
// Cooperative scan: 98 blocks (all resident on 148 SMs -> safe to spin).
// Computes g_dis, full exclusive scan of g_deg into g_row, g_row[NNODES].
__global__ void k_scan_all(int nblocks) {
    __shared__ int sh[1024];
    int b = blockIdx.x;
    int i = b * 1024 + threadIdx.x;
    int v = (i < NNODES) ? g_deg[i] : 0;
    if (i < NNODES) g_dis[i] = rsqrtf((float)v);
    sh[threadIdx.x] = v;
    __syncthreads();
    for (int off = 1; off < 1024; off <<= 1) {
        int t = (threadIdx.x >= off) ? sh[threadIdx.x - off] : 0;
        __syncthreads();
        sh[threadIdx.x] += t;
        __syncthreads();
    }
    int local_excl = sh[threadIdx.x] - v;
    if (threadIdx.x == 1023) {
        g_bsum[b] = sh[1023];
        __threadfence();
        atomicAdd(&g_arrive, 1);
    }
    // spin until all block totals posted (all blocks resident: no deadlock)
    if (threadIdx.x == 0) {
        volatile int* ar = &g_arrive;
        while (*ar < nblocks) { }
    }
    __syncthreads();
    // redundant per-block prefix over <=98 totals (cheap)
    int pre = 0;
    for (int g = 0; g < b; g++) pre += g_bsum[g];
    if (i < NNODES) g_row[i] = local_excl + pre;
    if (i == 0) g_row[NNODES] = TOTE;
}
__global__ void k_fill_csr(const int* __restrict__ ei) {
    int idx = blockIdx.x * blockDim.x + threadIdx.x;
    if (idx >= TOTE) return;
    int s, d;
    if (idx < NEDGES) { s = ei[idx]; d = ei[NEDGES + idx]; }
    else              { s = d = idx - NEDGES; }
    int pos = g_row[d] + atomicAdd(&g_cnt[d], 1);
    float w = g_dis[s] * g_dis[d];
    g_csr[pos] = make_int2(s, __float_as_int(w));
}

// ---------------- mma.sync bf16 GEMM: O[M,BN] = X[M,128] @ W[128,BN] ----------------
// 2-way bf16 split: O = Ah@Bh + Ah@Bl + Al@Bh (residual ~2^-16).
// K staged in two 64-wide chunks -> smem 72KB -> 2 CTAs/SM. LDA=72.
template<int BN>
__global__ __launch_bounds__(256, 2)
void k_mma_gemm(const float* __restrict__ X, const float* __restrict__ W,
                float* __restrict__ O, int M) {
    constexpr int LDA = 72;
    constexpr int ASZ = 128 * LDA;
    constexpr int BSZ = BN * LDA;
    constexpr int WM = (BN == 128) ? 2 : 4;
    constexpr int MT = 128 / WM / 16;
    constexpr int NT = 4;

    extern __shared__ __align__(16) __nv_bfloat16 smx[];
    __nv_bfloat16* Ah = smx;
    __nv_bfloat16* Al = Ah + ASZ;
    __nv_bfloat16* Bh = Al + ASZ;
    __nv_bfloat16* Bl = Bh + BSZ;

    int tid = threadIdx.x, wid = tid >> 5, lane = tid & 31;
    int brow = blockIdx.x * 128;

    int wm = wid % WM, wn = wid / WM;
    int rows0 = wm * (MT * 16);
    int col0  = wn * 32;

    int a_r = rows0 + (lane & 15);
    int a_c = (lane & 16) >> 1;
    int b_r = col0 + (lane & 7) + ((lane & 16) >> 1);
    int b_c = (lane & 8);
    uint32_t ah_base = smem_u32(Ah) + (uint32_t)(a_r * LDA + a_c) * 2;
    uint32_t al_base = smem_u32(Al) + (uint32_t)(a_r * LDA + a_c) * 2;
    uint32_t bh_base = smem_u32(Bh) + (uint32_t)(b_r * LDA + b_c) * 2;
    uint32_t bl_base = smem_u32(Bl) + (uint32_t)(b_r * LDA + b_c) * 2;

    float acc[MT][NT][4];
#pragma unroll
    for (int m = 0; m < MT; m++)
#pragma unroll
        for (int n = 0; n < NT; n++)
#pragma unroll
            for (int q = 0; q < 4; q++) acc[m][n][q] = 0.f;

    for (int kc = 0; kc < 128; kc += 64) {
        for (int idx = tid; idx < 128 * 16; idx += 256) {
            int r = idx >> 4, c4 = (idx & 15) * 4;
            float4 v = make_float4(0.f, 0.f, 0.f, 0.f);
            int gr = brow + r;
            if (gr < M) v = *(const float4*)(X + (size_t)gr * 128 + kc + c4);
            float f[4] = {v.x, v.y, v.z, v.w};
            __nv_bfloat16 h[4], l[4];
#pragma unroll
            for (int j = 0; j < 4; j++) {
                h[j] = __float2bfloat16_rn(f[j]);
                l[j] = __float2bfloat16_rn(f[j] - __bfloat162float(h[j]));
            }
            int o = r * LDA + c4;
            *(__nv_bfloat162*)(Ah + o)     = __nv_bfloat162(h[0], h[1]);
            *(__nv_bfloat162*)(Ah + o + 2) = __nv_bfloat162(h[2], h[3]);
            *(__nv_bfloat162*)(Al + o)     = __nv_bfloat162(l[0], l[1]);
            *(__nv_bfloat162*)(Al + o + 2) = __nv_bfloat162(l[2], l[3]);
        }
        for (int idx = tid; idx < 16 * BN; idx += 256) {
            int n  = idx % BN;
            int k0 = (idx / BN) * 4;
            float f[4];
#pragma unroll
            for (int j = 0; j < 4; j++) f[j] = W[(size_t)(kc + k0 + j) * BN + n];
            __nv_bfloat16 h[4], l[4];
#pragma unroll
            for (int j = 0; j < 4; j++) {
                h[j] = __float2bfloat16_rn(f[j]);
                l[j] = __float2bfloat16_rn(f[j] - __bfloat162float(h[j]));
            }
            int o = n * LDA + k0;
            *(__nv_bfloat162*)(Bh + o)     = __nv_bfloat162(h[0], h[1]);
            *(__nv_bfloat162*)(Bh + o + 2) = __nv_bfloat162(h[2], h[3]);
            *(__nv_bfloat162*)(Bl + o)     = __nv_bfloat162(l[0], l[1]);
            *(__nv_bfloat162*)(Bl + o + 2) = __nv_bfloat162(l[2], l[3]);
        }
        __syncthreads();

#pragma unroll
        for (int ks = 0; ks < 4; ks++) {
            uint32_t koff = (uint32_t)(ks * 16) * 2;
            uint32_t ah[MT][4], al[MT][4], bh[2][4], bl[2][4];
#pragma unroll
            for (int m = 0; m < MT; m++) {
                uint32_t moff = (uint32_t)(m * 16 * LDA) * 2;
                ldsm_x4(ah[m], ah_base + moff + koff);
                ldsm_x4(al[m], al_base + moff + koff);
            }
#pragma unroll
            for (int p = 0; p < 2; p++) {
                uint32_t poff = (uint32_t)(p * 16 * LDA) * 2;
                ldsm_x4(bh[p], bh_base + poff + koff);
                ldsm_x4(bl[p], bl_base + poff + koff);
            }
#pragma unroll
            for (int m = 0; m < MT; m++) {
#pragma unroll
                for (int p = 0; p < 2; p++) {
                    mma_bf16(acc[m][2 * p],     ah[m], &bh[p][0]);
                    mma_bf16(acc[m][2 * p],     ah[m], &bl[p][0]);
                    mma_bf16(acc[m][2 * p],     al[m], &bh[p][0]);
                    mma_bf16(acc[m][2 * p + 1], ah[m], &bh[p][2]);
                    mma_bf16(acc[m][2 * p + 1], ah[m], &bl[p][2]);
                    mma_bf16(acc[m][2 * p + 1], al[m], &bh[p][2]);
                }
            }
        }
        __syncthreads();
    }

    int gid  = lane >> 2;
    int quad = lane & 3;
#pragma unroll
    for (int m = 0; m < MT; m++) {
        int r0 = brow + rows0 + m * 16 + gid;
#pragma unroll
        for (int n = 0; n < NT; n++) {
            int c = col0 + n * 8 + quad * 2;
            if (r0 < M)
                *(float2*)(O + (size_t)r0 * BN + c) = make_float2(acc[m][n][0], acc[m][n][1]);
            if (r0 + 8 < M)
                *(float2*)(O + (size_t)(r0 + 8) * BN + c) = make_float2(acc[m][n][2], acc[m][n][3]);
        }
    }
}

// ---------------- aggregation (128-wide): 4 warps per node, 128B quarter-rows ----------------
template<bool RELU>
__global__ __launch_bounds__(256)
void k_aggregate128(const float* __restrict__ h, const float* __restrict__ bias,
                    float* __restrict__ out) {
    int gw   = (blockIdx.x * blockDim.x + threadIdx.x) >> 5;
    int lane = threadIdx.x & 31;
    int node = gw >> 2;
    int quarter = gw & 3;
    if (node >= NNODES) return;
    const float* hh = h + quarter * 32;
    int e = g_row[node], end = g_row[node + 1];
    float acc = 0.f;
    for (; e + 8 <= end; e += 8) {
        int2 p[8];
#pragma unroll
        for (int j = 0; j < 8; j++) p[j] = g_csr[e + j];
        float v[8];
#pragma unroll
        for (int j = 0; j < 8; j++) v[j] = hh[(size_t)p[j].x * 128 + lane];
#pragma unroll
        for (int j = 0; j < 8; j++) acc = fmaf(__int_as_float(p[j].y), v[j], acc);
    }
    for (; e + 4 <= end; e += 4) {
        int2 p[4];
#pragma unroll
        for (int j = 0; j < 4; j++) p[j] = g_csr[e + j];
        float v[4];
#pragma unroll
        for (int j = 0; j < 4; j++) v[j] = hh[(size_t)p[j].x * 128 + lane];
#pragma unroll
        for (int j = 0; j < 4; j++) acc = fmaf(__int_as_float(p[j].y), v[j], acc);
    }
    for (; e < end; e++) {
        int2 p = g_csr[e];
        acc = fmaf(__int_as_float(p.y), hh[(size_t)p.x * 128 + lane], acc);
    }
    acc += bias[quarter * 32 + lane];
    if (RELU) acc = fmaxf(acc, 0.f);
    out[(size_t)node * 128 + quarter * 32 + lane] = acc;
}

// ---------------- aggregation (64-wide): 2 warps per node, 128B half-rows ----------------
template<bool RELU>
__global__ __launch_bounds__(256)
void k_aggregate64(const float* __restrict__ h, const float* __restrict__ bias,
                   float* __restrict__ out) {
    int gw   = (blockIdx.x * blockDim.x + threadIdx.x) >> 5;
    int lane = threadIdx.x & 31;
    int node = gw >> 1;
    int half = gw & 1;
    if (node >= NNODES) return;
    const float* hh = h + half * 32;
    int e = g_row[node], end = g_row[node + 1];
    float acc = 0.f;
    for (; e + 8 <= end; e += 8) {
        int2 p[8];
#pragma unroll
        for (int j = 0; j < 8; j++) p[j] = g_csr[e + j];
        float v[8];
#pragma unroll
        for (int j = 0; j < 8; j++) v[j] = hh[(size_t)p[j].x * 64 + lane];
#pragma unroll
        for (int j = 0; j < 8; j++) acc = fmaf(__int_as_float(p[j].y), v[j], acc);
    }
    for (; e + 4 <= end; e += 4) {
        int2 p[4];
#pragma unroll
        for (int j = 0; j < 4; j++) p[j] = g_csr[e + j];
        float v[4];
#pragma unroll
        for (int j = 0; j < 4; j++) v[j] = hh[(size_t)p[j].x * 64 + lane];
#pragma unroll
        for (int j = 0; j < 4; j++) acc = fmaf(__int_as_float(p[j].y), v[j], acc);
    }
    for (; e < end; e++) {
        int2 p = g_csr[e];
        acc = fmaf(__int_as_float(p.y), hh[(size_t)p.x * 64 + lane], acc);
    }
    acc += bias[half * 32 + lane];
    if (RELU) acc = fmaxf(acc, 0.f);
    out[(size_t)node * 64 + half * 32 + lane] = acc;
}

// ---------------- decode (s,q packed into one 64-bit shfl chain) ----------------
__global__ __launch_bounds__(256)
void k_decode(const float* __restrict__ z, const int* __restrict__ eli,
              float* __restrict__ out) {
    int w    = (blockIdx.x * blockDim.x + threadIdx.x) >> 5;
    int lane = threadIdx.x & 31;
    if (w >= NLAB) return;
    int a = eli[w];
    int b = eli[NLAB + w];
    float2 za = *(const float2*)(z + (size_t)a * 64 + lane * 2);
    float2 zb = *(const float2*)(z + (size_t)b * 64 + lane * 2);
    float h0 = za.x * zb.x;
    float h1 = za.y * zb.y;
    float s  = h0 + h1;
    float q  = h0 * h0 + h1 * h1;
#pragma unroll
    for (int off = 16; off > 0; off >>= 1) {
        unsigned long long pk;
        asm("mov.b64 %0, {%1, %2};" : "=l"(pk) : "f"(s), "f"(q));
        unsigned long long other = __shfl_xor_sync(0xFFFFFFFFu, pk, off);
        float os, oq;
        asm("mov.b64 {%0, %1}, %2;" : "=f"(os), "=f"(oq) : "l"(other));
        s += os; q += oq;
    }
    float nrm = fmaxf(sqrtf(q), 1e-12f);
    float inv = 1.0f / nrm;
    *(float2*)(out + (size_t)w * 64 + lane * 2) = make_float2(h0 * inv, h1 * inv);
    if (lane == 0) out[(size_t)NLAB * 64 + w] = s;
}

// ---------------- launch ----------------
extern "C" void kernel_launch(void* const* d_in, const int* in_sizes, int n_in,
                              void* d_out, int out_size) {
    const float* x  = (const float*)d_in[0];
    const float* W1 = (const float*)d_in[1];
    const float* b1 = (const float*)d_in[2];
    const float* W2 = (const float*)d_in[3];
    const float* b2 = (const float*)d_in[4];
    const float* W3 = (const float*)d_in[5];
    const float* b3 = (const float*)d_in[6];
    const int*   ei  = (const int*)d_in[7];
    const int*   eli = (const int*)d_in[8];
    float* out = (float*)d_out;

    float* bufA = nullptr;
    float* bufB = nullptr;
    cudaGetSymbolAddress((void**)&bufA, g_bufA);
    cudaGetSymbolAddress((void**)&bufB, g_bufB);

    const int SMEM128 = (2 * 128 * 72 + 2 * 128 * 72) * 2;   // 73728 B
    const int SMEM64  = (2 * 128 * 72 + 2 * 64 * 72) * 2;    // 55296 B

    // One-time init: first call is the eager correctness run (not under
    // capture). Stream/event creation and func attributes happen here only.
    static cudaStream_t s2 = nullptr;
    static cudaEvent_t ev0 = nullptr, ev1 = nullptr;
    if (s2 == nullptr) {
        cudaStreamCreateWithFlags(&s2, cudaStreamNonBlocking);
        cudaEventCreateWithFlags(&ev0, cudaEventDisableTiming);
        cudaEventCreateWithFlags(&ev1, cudaEventDisableTiming);
        cudaFuncSetAttribute(k_mma_gemm<128>, cudaFuncAttributeMaxDynamicSharedMemorySize, SMEM128);
        cudaFuncSetAttribute(k_mma_gemm<64>,  cudaFuncAttributeMaxDynamicSharedMemorySize, SMEM64);
    }

    const int nscan = (NNODES + 1023) / 1024;             // 98 (<148 SMs: all resident)
    const int gemm_grid   = (NNODES + 127) / 128;         // 782
    const int agg128_grid = (NNODES * 128 + 255) / 256;   // 50000 (4 warps/node)
    const int agg64_grid  = (NNODES * 64 + 255) / 256;    // 25000 (2 warps/node)
    const int dec_grid    = (NLAB * 32 + 255) / 256;      // 25000

    // Fork: CSR build on s2, GEMM1 on default stream (independent work).
    cudaEventRecord(ev0, 0);
    cudaStreamWaitEvent(s2, ev0, 0);

    k_init<<<(NNODES + 255) / 256, 256, 0, s2>>>();
    k_count<<<(NEDGES + 255) / 256, 256, 0, s2>>>(ei);
    k_scan_all<<<nscan, 1024, 0, s2>>>(nscan);

    k_mma_gemm<128><<<gemm_grid, 256, SMEM128>>>(x, W1, bufB, NNODES);

    k_fill_csr<<<(TOTE + 255) / 256, 256, 0, s2>>>(ei);
    cudaEventRecord(ev1, s2);
    cudaStreamWaitEvent(0, ev1, 0);

    k_aggregate128<true><<<agg128_grid, 256>>>(bufB, b1, bufA);
    k_mma_gemm<128><<<gemm_grid, 256, SMEM128>>>(bufA, W2, bufB, NNODES);
    k_aggregate128<true><<<agg128_grid, 256>>>(bufB, b2, bufA);
    k_mma_gemm<64><<<gemm_grid, 256, SMEM64>>>(bufA, W3, bufB, NNODES);
    k_aggregate64<false><<<agg64_grid, 256>>>(bufB, b3, bufA);
    k_decode<<<dec_grid, 256>>>(bufA, eli, out);
}

// round 13
// speedup vs baseline: 1.2815x; 1.2815x over previous
#include <cuda_runtime.h>
#include <cuda_bf16.h>
#include <math.h>
#include <stdint.h>

#define NNODES 100000
#define NEDGES 1600000
#define NLAB   200000
#define TOTE   (NEDGES + NNODES)

// ---------------- scratch (device globals; no allocation allowed) ----------------
__device__ int   g_deg[NNODES];
__device__ float g_dis[NNODES];
__device__ int   g_row[NNODES + 1];
__device__ int   g_cnt[NNODES];
__device__ int   g_bsum[128];
__device__ int2  g_csr[TOTE];            // packed (src, weight-bits)
__device__ float g_bufA[(size_t)NNODES * 128];
__device__ float g_bufB[(size_t)NNODES * 128];

// ---------------- warp-mma helpers (sm_80+ baseline ISA; no 'a' features) ----------------
__device__ __forceinline__ uint32_t smem_u32(const void* p) {
    uint32_t a;
    asm("{ .reg .u64 t; cvta.to.shared.u64 t, %1; cvt.u32.u64 %0, t; }" : "=r"(a) : "l"(p));
    return a;
}
__device__ __forceinline__ void ldsm_x4(uint32_t* r, uint32_t addr) {
    asm volatile("ldmatrix.sync.aligned.m8n8.x4.shared.b16 {%0,%1,%2,%3}, [%4];"
        : "=r"(r[0]), "=r"(r[1]), "=r"(r[2]), "=r"(r[3]) : "r"(addr));
}
__device__ __forceinline__ void mma_bf16(float* c, const uint32_t* a, const uint32_t* b) {
    asm volatile("mma.sync.aligned.m16n8k16.row.col.f32.bf16.bf16.f32 "
        "{%0,%1,%2,%3}, {%4,%5,%6,%7}, {%8,%9}, {%0,%1,%2,%3};"
        : "+f"(c[0]), "+f"(c[1]), "+f"(c[2]), "+f"(c[3])
        : "r"(a[0]), "r"(a[1]), "r"(a[2]), "r"(a[3]), "r"(b[0]), "r"(b[1]));
}
// pack (f0,f1) -> bf16x2 (f0 in low half), then split hi/lo planes
__device__ __forceinline__ void split2(float f0, float f1, uint32_t& ph, uint32_t& pl) {
    asm("cvt.rn.bf16x2.f32 %0, %1, %2;" : "=r"(ph) : "f"(f1), "f"(f0));
    float h0 = __uint_as_float(ph << 16);
    float h1 = __uint_as_float(ph & 0xFFFF0000u);
    float l0 = f0 - h0, l1 = f1 - h1;
    asm("cvt.rn.bf16x2.f32 %0, %1, %2;" : "=r"(pl) : "f"(l1), "f"(l0));
}

// ---------------- CSR build ----------------
__global__ void k_init(void) {
    int i = blockIdx.x * blockDim.x + threadIdx.x;
    if (i < NNODES) { g_deg[i] = 1; g_cnt[i] = 0; }
}
__global__ void k_count(const int* __restrict__ ei) {
    int e = blockIdx.x * blockDim.x + threadIdx.x;
    if (e < NEDGES) atomicAdd(&g_deg[ei[NEDGES + e]], 1);
}
__global__ void k_scan_blocks(void) {       // also computes g_dis (deg is final here)
    __shared__ int sh[1024];
    int i = blockIdx.x * 1024 + threadIdx.x;
    int v = (i < NNODES) ? g_deg[i] : 0;
    if (i < NNODES) g_dis[i] = rsqrtf((float)v);
    sh[threadIdx.x] = v;
    __syncthreads();
    for (int off = 1; off < 1024; off <<= 1) {
        int t = (threadIdx.x >= off) ? sh[threadIdx.x - off] : 0;
        __syncthreads();
        sh[threadIdx.x] += t;
        __syncthreads();
    }
    if (i < NNODES) g_row[i] = sh[threadIdx.x] - v;
    if (threadIdx.x == 1023) g_bsum[blockIdx.x] = sh[1023];
}
__global__ void k_scan_sums2(int nblocks) {     // parallel 128-wide scan
    __shared__ int sh[128];
    int t = threadIdx.x;
    int v = (t < nblocks) ? g_bsum[t] : 0;
    sh[t] = v;
    __syncthreads();
    for (int off = 1; off < 128; off <<= 1) {
        int u = (t >= off) ? sh[t - off] : 0;
        __syncthreads();
        sh[t] += u;
        __syncthreads();
    }
    if (t < nblocks) g_bsum[t] = sh[t] - v;     // exclusive
}
__global__ void k_add_off(void) {
    int i = blockIdx.x * blockDim.x + threadIdx.x;
    if (i < NNODES) g_row[i] += g_bsum[i >> 10];
    if (i == 0) g_row[NNODES] = TOTE;
}
__global__ void k_fill_csr(const int* __restrict__ ei) {
    int idx = blockIdx.x * blockDim.x + threadIdx.x;
    if (idx >= TOTE) return;
    int s, d;
    if (idx < NEDGES) { s = ei[idx]; d = ei[NEDGES + idx]; }
    else              { s = d = idx - NEDGES; }
    int pos = g_row[d] + atomicAdd(&g_cnt[d], 1);
    float w = g_dis[s] * g_dis[d];
    g_csr[pos] = make_int2(s, __float_as_int(w));
}

// ---------------- mma.sync bf16 GEMM: O[M,BN] = X[M,128] @ W[128,BN] ----------------
// 2-way bf16 split: O = Ah@Bh + Ah@Bl + Al@Bh (residual ~2^-16).
// K staged in two 64-wide chunks -> smem 72KB -> 2 CTAs/SM. LDA=72.
template<int BN>
__global__ __launch_bounds__(256, 2)
void k_mma_gemm(const float* __restrict__ X, const float* __restrict__ W,
                float* __restrict__ O, int M) {
    constexpr int LDA = 72;
    constexpr int ASZ = 128 * LDA;
    constexpr int BSZ = BN * LDA;
    constexpr int WM = (BN == 128) ? 2 : 4;
    constexpr int MT = 128 / WM / 16;
    constexpr int NT = 4;

    extern __shared__ __align__(16) __nv_bfloat16 smx[];
    __nv_bfloat16* Ah = smx;
    __nv_bfloat16* Al = Ah + ASZ;
    __nv_bfloat16* Bh = Al + ASZ;
    __nv_bfloat16* Bl = Bh + BSZ;

    int tid = threadIdx.x, wid = tid >> 5, lane = tid & 31;
    int brow = blockIdx.x * 128;

    int wm = wid % WM, wn = wid / WM;
    int rows0 = wm * (MT * 16);
    int col0  = wn * 32;

    int a_r = rows0 + (lane & 15);
    int a_c = (lane & 16) >> 1;
    int b_r = col0 + (lane & 7) + ((lane & 16) >> 1);
    int b_c = (lane & 8);
    uint32_t ah_base = smem_u32(Ah) + (uint32_t)(a_r * LDA + a_c) * 2;
    uint32_t al_base = smem_u32(Al) + (uint32_t)(a_r * LDA + a_c) * 2;
    uint32_t bh_base = smem_u32(Bh) + (uint32_t)(b_r * LDA + b_c) * 2;
    uint32_t bl_base = smem_u32(Bl) + (uint32_t)(b_r * LDA + b_c) * 2;

    float acc[MT][NT][4];
#pragma unroll
    for (int m = 0; m < MT; m++)
#pragma unroll
        for (int n = 0; n < NT; n++)
#pragma unroll
            for (int q = 0; q < 4; q++) acc[m][n][q] = 0.f;

    for (int kc = 0; kc < 128; kc += 64) {
        // ---- stage A chunk (packed bf16x2 split) ----
        for (int idx = tid; idx < 128 * 16; idx += 256) {
            int r = idx >> 4, c4 = (idx & 15) * 4;
            float4 v = make_float4(0.f, 0.f, 0.f, 0.f);
            int gr = brow + r;
            if (gr < M) v = *(const float4*)(X + (size_t)gr * 128 + kc + c4);
            uint32_t h01, l01, h23, l23;
            split2(v.x, v.y, h01, l01);
            split2(v.z, v.w, h23, l23);
            int o = r * LDA + c4;
            *(uint32_t*)(Ah + o)     = h01;
            *(uint32_t*)(Ah + o + 2) = h23;
            *(uint32_t*)(Al + o)     = l01;
            *(uint32_t*)(Al + o + 2) = l23;
        }
        // ---- stage B chunk transposed ----
        for (int idx = tid; idx < 16 * BN; idx += 256) {
            int n  = idx % BN;
            int k0 = (idx / BN) * 4;
            float f[4];
#pragma unroll
            for (int j = 0; j < 4; j++) f[j] = W[(size_t)(kc + k0 + j) * BN + n];
            uint32_t h01, l01, h23, l23;
            split2(f[0], f[1], h01, l01);
            split2(f[2], f[3], h23, l23);
            int o = n * LDA + k0;
            *(uint32_t*)(Bh + o)     = h01;
            *(uint32_t*)(Bh + o + 2) = h23;
            *(uint32_t*)(Bl + o)     = l01;
            *(uint32_t*)(Bl + o + 2) = l23;
        }
        __syncthreads();

#pragma unroll
        for (int ks = 0; ks < 4; ks++) {
            uint32_t koff = (uint32_t)(ks * 16) * 2;
            uint32_t ah[MT][4], al[MT][4], bh[2][4], bl[2][4];
#pragma unroll
            for (int m = 0; m < MT; m++) {
                uint32_t moff = (uint32_t)(m * 16 * LDA) * 2;
                ldsm_x4(ah[m], ah_base + moff + koff);
                ldsm_x4(al[m], al_base + moff + koff);
            }
#pragma unroll
            for (int p = 0; p < 2; p++) {
                uint32_t poff = (uint32_t)(p * 16 * LDA) * 2;
                ldsm_x4(bh[p], bh_base + poff + koff);
                ldsm_x4(bl[p], bl_base + poff + koff);
            }
#pragma unroll
            for (int m = 0; m < MT; m++) {
#pragma unroll
                for (int p = 0; p < 2; p++) {
                    mma_bf16(acc[m][2 * p],     ah[m], &bh[p][0]);
                    mma_bf16(acc[m][2 * p],     ah[m], &bl[p][0]);
                    mma_bf16(acc[m][2 * p],     al[m], &bh[p][0]);
                    mma_bf16(acc[m][2 * p + 1], ah[m], &bh[p][2]);
                    mma_bf16(acc[m][2 * p + 1], ah[m], &bl[p][2]);
                    mma_bf16(acc[m][2 * p + 1], al[m], &bh[p][2]);
                }
            }
        }
        __syncthreads();
    }

    int gid  = lane >> 2;
    int quad = lane & 3;
#pragma unroll
    for (int m = 0; m < MT; m++) {
        int r0 = brow + rows0 + m * 16 + gid;
#pragma unroll
        for (int n = 0; n < NT; n++) {
            int c = col0 + n * 8 + quad * 2;
            if (r0 < M)
                *(float2*)(O + (size_t)r0 * BN + c) = make_float2(acc[m][n][0], acc[m][n][1]);
            if (r0 + 8 < M)
                *(float2*)(O + (size_t)(r0 + 8) * BN + c) = make_float2(acc[m][n][2], acc[m][n][3]);
        }
    }
}

// ---------------- aggregation (128-wide): 2 warps per node, 8-deep pipeline ----------------
template<bool RELU>
__global__ __launch_bounds__(256)
void k_aggregate128(const float* __restrict__ h, const float* __restrict__ bias,
                    float* __restrict__ out) {
    int gw   = (blockIdx.x * blockDim.x + threadIdx.x) >> 5;
    int lane = threadIdx.x & 31;
    int node = gw >> 1;
    int half = gw & 1;
    if (node >= NNODES) return;
    const float* hh = h + half * 64;
    int e = g_row[node], end = g_row[node + 1];
    float2 acc = make_float2(0.f, 0.f);
    for (; e + 8 <= end; e += 8) {
        int2 p[8];
#pragma unroll
        for (int j = 0; j < 8; j++) p[j] = g_csr[e + j];
        float2 v[8];
#pragma unroll
        for (int j = 0; j < 8; j++) v[j] = *(const float2*)(hh + (size_t)p[j].x * 128 + lane * 2);
#pragma unroll
        for (int j = 0; j < 8; j++) {
            float wt = __int_as_float(p[j].y);
            acc.x = fmaf(wt, v[j].x, acc.x);
            acc.y = fmaf(wt, v[j].y, acc.y);
        }
    }
    for (; e + 4 <= end; e += 4) {
        int2 p[4];
#pragma unroll
        for (int j = 0; j < 4; j++) p[j] = g_csr[e + j];
        float2 v[4];
#pragma unroll
        for (int j = 0; j < 4; j++) v[j] = *(const float2*)(hh + (size_t)p[j].x * 128 + lane * 2);
#pragma unroll
        for (int j = 0; j < 4; j++) {
            float wt = __int_as_float(p[j].y);
            acc.x = fmaf(wt, v[j].x, acc.x);
            acc.y = fmaf(wt, v[j].y, acc.y);
        }
    }
    for (; e < end; e++) {
        int2 p = g_csr[e];
        float wt = __int_as_float(p.y);
        float2 v = *(const float2*)(hh + (size_t)p.x * 128 + lane * 2);
        acc.x = fmaf(wt, v.x, acc.x); acc.y = fmaf(wt, v.y, acc.y);
    }
    float2 bb = *(const float2*)(bias + half * 64 + lane * 2);
    acc.x += bb.x; acc.y += bb.y;
    if (RELU) { acc.x = fmaxf(acc.x, 0.f); acc.y = fmaxf(acc.y, 0.f); }
    *(float2*)(out + (size_t)node * 128 + half * 64 + lane * 2) = acc;
}

// ---------------- aggregation (64-wide): 1 warp per node, 8-deep pipeline ----------------
template<bool RELU>
__global__ __launch_bounds__(256)
void k_aggregate64(const float* __restrict__ h, const float* __restrict__ bias,
                   float* __restrict__ out) {
    int w    = (blockIdx.x * blockDim.x + threadIdx.x) >> 5;
    int lane = threadIdx.x & 31;
    if (w >= NNODES) return;
    int e = g_row[w], end = g_row[w + 1];
    float2 acc = make_float2(0.f, 0.f);
    for (; e + 8 <= end; e += 8) {
        int2 p[8];
#pragma unroll
        for (int j = 0; j < 8; j++) p[j] = g_csr[e + j];
        float2 v[8];
#pragma unroll
        for (int j = 0; j < 8; j++) v[j] = *(const float2*)(h + (size_t)p[j].x * 64 + lane * 2);
#pragma unroll
        for (int j = 0; j < 8; j++) {
            float wt = __int_as_float(p[j].y);
            acc.x = fmaf(wt, v[j].x, acc.x);
            acc.y = fmaf(wt, v[j].y, acc.y);
        }
    }
    for (; e + 4 <= end; e += 4) {
        int2 p[4];
#pragma unroll
        for (int j = 0; j < 4; j++) p[j] = g_csr[e + j];
        float2 v[4];
#pragma unroll
        for (int j = 0; j < 4; j++) v[j] = *(const float2*)(h + (size_t)p[j].x * 64 + lane * 2);
#pragma unroll
        for (int j = 0; j < 4; j++) {
            float wt = __int_as_float(p[j].y);
            acc.x = fmaf(wt, v[j].x, acc.x);
            acc.y = fmaf(wt, v[j].y, acc.y);
        }
    }
    for (; e < end; e++) {
        int2 p = g_csr[e];
        float wt = __int_as_float(p.y);
        float2 v = *(const float2*)(h + (size_t)p.x * 64 + lane * 2);
        acc.x = fmaf(wt, v.x, acc.x); acc.y = fmaf(wt, v.y, acc.y);
    }
    float2 bb = *(const float2*)(bias + lane * 2);
    acc.x += bb.x; acc.y += bb.y;
    if (RELU) { acc.x = fmaxf(acc.x, 0.f); acc.y = fmaxf(acc.y, 0.f); }
    *(float2*)(out + (size_t)w * 64 + lane * 2) = acc;
}

// ---------------- decode (s,q packed into one 64-bit shfl chain) ----------------
__global__ __launch_bounds__(256)
void k_decode(const float* __restrict__ z, const int* __restrict__ eli,
              float* __restrict__ out) {
    int w    = (blockIdx.x * blockDim.x + threadIdx.x) >> 5;
    int lane = threadIdx.x & 31;
    if (w >= NLAB) return;
    int a = eli[w];
    int b = eli[NLAB + w];
    float2 za = *(const float2*)(z + (size_t)a * 64 + lane * 2);
    float2 zb = *(const float2*)(z + (size_t)b * 64 + lane * 2);
    float h0 = za.x * zb.x;
    float h1 = za.y * zb.y;
    float s  = h0 + h1;
    float q  = h0 * h0 + h1 * h1;
#pragma unroll
    for (int off = 16; off > 0; off >>= 1) {
        unsigned long long pk;
        asm("mov.b64 %0, {%1, %2};" : "=l"(pk) : "f"(s), "f"(q));
        unsigned long long other = __shfl_xor_sync(0xFFFFFFFFu, pk, off);
        float os, oq;
        asm("mov.b64 {%0, %1}, %2;" : "=f"(os), "=f"(oq) : "l"(other));
        s += os; q += oq;
    }
    float nrm = fmaxf(sqrtf(q), 1e-12f);
    float inv = 1.0f / nrm;
    *(float2*)(out + (size_t)w * 64 + lane * 2) = make_float2(h0 * inv, h1 * inv);
    if (lane == 0) out[(size_t)NLAB * 64 + w] = s;
}

// ---------------- launch ----------------
extern "C" void kernel_launch(void* const* d_in, const int* in_sizes, int n_in,
                              void* d_out, int out_size) {
    const float* x  = (const float*)d_in[0];
    const float* W1 = (const float*)d_in[1];
    const float* b1 = (const float*)d_in[2];
    const float* W2 = (const float*)d_in[3];
    const float* b2 = (const float*)d_in[4];
    const float* W3 = (const float*)d_in[5];
    const float* b3 = (const float*)d_in[6];
    const int*   ei  = (const int*)d_in[7];
    const int*   eli = (const int*)d_in[8];
    float* out = (float*)d_out;

    float* bufA = nullptr;
    float* bufB = nullptr;
    cudaGetSymbolAddress((void**)&bufA, g_bufA);
    cudaGetSymbolAddress((void**)&bufB, g_bufB);

    const int SMEM128 = (2 * 128 * 72 + 2 * 128 * 72) * 2;   // 73728 B
    const int SMEM64  = (2 * 128 * 72 + 2 * 64 * 72) * 2;    // 55296 B

    // One-time init: first call is the eager correctness run (not under
    // capture). Stream/event creation and func attributes happen here only.
    static cudaStream_t s2 = nullptr;
    static cudaEvent_t ev0 = nullptr, ev1 = nullptr;
    if (s2 == nullptr) {
        cudaStreamCreateWithFlags(&s2, cudaStreamNonBlocking);
        cudaEventCreateWithFlags(&ev0, cudaEventDisableTiming);
        cudaEventCreateWithFlags(&ev1, cudaEventDisableTiming);
        cudaFuncSetAttribute(k_mma_gemm<128>, cudaFuncAttributeMaxDynamicSharedMemorySize, SMEM128);
        cudaFuncSetAttribute(k_mma_gemm<64>,  cudaFuncAttributeMaxDynamicSharedMemorySize, SMEM64);
    }

    const int nscan = (NNODES + 1023) / 1024;             // 98
    const int gemm_grid  = (NNODES + 127) / 128;          // 782
    const int agg_grid   = (NNODES * 64 + 255) / 256;     // 25000 (2 warps/node)
    const int agg64_grid = (NNODES * 32 + 255) / 256;     // 12500
    const int dec_grid   = (NLAB * 32 + 255) / 256;       // 25000

    // Fork: CSR build on s2, GEMM1 on default stream (independent work).
    cudaEventRecord(ev0, 0);
    cudaStreamWaitEvent(s2, ev0, 0);

    k_init<<<(NNODES + 255) / 256, 256, 0, s2>>>();
    k_count<<<(NEDGES + 255) / 256, 256, 0, s2>>>(ei);
    k_scan_blocks<<<nscan, 1024, 0, s2>>>();
    k_scan_sums2<<<1, 128, 0, s2>>>(nscan);

    k_mma_gemm<128><<<gemm_grid, 256, SMEM128>>>(x, W1, bufB, NNODES);

    k_add_off<<<(NNODES + 255) / 256, 256, 0, s2>>>();
    k_fill_csr<<<(TOTE + 255) / 256, 256, 0, s2>>>(ei);
    cudaEventRecord(ev1, s2);
    cudaStreamWaitEvent(0, ev1, 0);

    k_aggregate128<true><<<agg_grid, 256>>>(bufB, b1, bufA);
    k_mma_gemm<128><<<gemm_grid, 256, SMEM128>>>(bufA, W2, bufB, NNODES);
    k_aggregate128<true><<<agg_grid, 256>>>(bufB, b2, bufA);
    k_mma_gemm<64><<<gemm_grid, 256, SMEM64>>>(bufA, W3, bufB, NNODES);
    k_aggregate64<false><<<agg64_grid, 256>>>(bufB, b3, bufA);
    k_decode<<<dec_grid, 256>>>(bufA, eli, out);
}